// round 4
// baseline (speedup 1.0000x reference)
#include <cuda_runtime.h>

// CorrectedPartialCharges:
//   out[i] = x[i] + (total_charge[g] - sum_{j in g} x[j]) / n_atoms[g],  g = i / 256
//
// One graph per HALF-WARP (16 lanes x 16 floats): 4 front-batched LDG.128,
// 4-stage xor-shuffle reduction within the 16-lane group, 4x STG.128.
// NEW vs round 3: output stores are STREAMING (__stcs / .cs evict-first).
// The output buffer is write-only and never re-read; with default policy its
// 33.5 MB of dirty lines pollute L2 and evict the (reused-across-replays)
// input, forcing steady-state DRAM re-reads. Evict-first stores keep the
// input L2-resident, cutting warm-loop DRAM traffic toward writeback-only.

static constexpr int ATOMS_PER_GRAPH   = 256;
static constexpr int THREADS_PER_BLOCK = 256;
static constexpr int GRAPHS_PER_BLOCK  = THREADS_PER_BLOCK / 16;   // 16

__global__ __launch_bounds__(THREADS_PER_BLOCK, 8)
void corrected_partial_charges_kernel(
    const float* __restrict__ node_outputs,   // [N]
    const float* __restrict__ total_charge,   // [B]
    const int*   __restrict__ n_atoms,        // [B]
    float*       __restrict__ out,            // [N]
    int n_graphs)
{
    const int tid    = threadIdx.x;
    const int lane16 = tid & 15;                       // lane within half-warp
    const int g = blockIdx.x * GRAPHS_PER_BLOCK + (tid >> 4);
    if (g >= n_graphs) return;

    const size_t base = (size_t)g * ATOMS_PER_GRAPH;   // in floats
    const float4* __restrict__ in4 = reinterpret_cast<const float4*>(node_outputs + base);
    float4*       __restrict__ o4  = reinterpret_cast<float4*>(out + base);

    // 4 front-batched 16B loads per lane: graph spans float4 [0,64)
    float4 a = in4[lane16];
    float4 b = in4[lane16 + 16];
    float4 c = in4[lane16 + 32];
    float4 d = in4[lane16 + 48];

    const float tc = __ldg(total_charge + g);
    const float na = (float)__ldg(n_atoms + g);

    float s = ((a.x + a.y) + (a.z + a.w)) + ((b.x + b.y) + (b.z + b.w))
            + ((c.x + c.y) + (c.z + c.w)) + ((d.x + d.y) + (d.z + d.w));

    // 4-stage butterfly within the 16-lane group
    #pragma unroll
    for (int off = 8; off > 0; off >>= 1)
        s += __shfl_xor_sync(0xffffffffu, s, off);

    const float leftover = (tc - s) / na;

    a.x += leftover; a.y += leftover; a.z += leftover; a.w += leftover;
    b.x += leftover; b.y += leftover; b.z += leftover; b.w += leftover;
    c.x += leftover; c.y += leftover; c.z += leftover; c.w += leftover;
    d.x += leftover; d.y += leftover; d.z += leftover; d.w += leftover;

    // Streaming (evict-first) stores: output is write-only, don't let it
    // displace the input's L2 residency.
    __stcs(&o4[lane16],      a);
    __stcs(&o4[lane16 + 16], b);
    __stcs(&o4[lane16 + 32], c);
    __stcs(&o4[lane16 + 48], d);
}

extern "C" void kernel_launch(void* const* d_in, const int* in_sizes, int n_in,
                              void* d_out, int out_size)
{
    // metadata order: node_outputs [N,1] f32, total_charge [B] f32,
    //                 batch [N] i32 (unused: structure static), n_atoms [B] i32
    const float* node_outputs = (const float*)d_in[0];
    const float* total_charge = (const float*)d_in[1];
    const int*   n_atoms      = (const int*)d_in[3];
    float*       out          = (float*)d_out;

    const int n_graphs = in_sizes[1];                 // 32768
    const int blocks = (n_graphs + GRAPHS_PER_BLOCK - 1) / GRAPHS_PER_BLOCK;

    corrected_partial_charges_kernel<<<blocks, THREADS_PER_BLOCK>>>(
        node_outputs, total_charge, n_atoms, out, n_graphs);
}